// round 14
// baseline (speedup 1.0000x reference)
#include <cuda_runtime.h>
#include <cuda_bf16.h>
#include <math.h>

#define BATCH 4
#define CH 96
#define IMG 256
#define WSZ 8
#define NWIN 1024          // 32x32 windows per image
#define NTOK 64
#define NHEADS 6
#define HD 16
#define PDIM 30
#define EPSV 1e-8f
#define NPIX (BATCH*IMG*IMG)        // 262144
#define NWTOT (BATCH*NWIN)          // 4096
#define FEAT (NTOK*CH)              // 6144
#define QSZ ((size_t)NWTOT*NTOK*CH) // 25165824

// ---------------- scratch (static device globals; no allocation) ----------------
__device__ float g_q[QSZ];       // later: S = conv_out + attn_out (pixel-major)
__device__ float g_k[QSZ];       // later: rw (global-attention output)
__device__ float g_v[QSZ];
#define g_S  g_q
#define g_rw g_k
__device__ float g_H[(size_t)NWTOT*256];
__device__ float g_Hp[(size_t)4*NWTOT*256];      // split-K partials for gemm1
__device__ float g_embT[(size_t)PDIM*NWTOT];     // transposed: [PDIM][NWTOT]
__device__ float g_bias[NHEADS*NTOK*NTOK];
__device__ double g_ssum[BATCH], g_ssq[BATCH], g_csum[BATCH], g_csq[BATCH];
__device__ float g_scale[BATCH], g_shift[BATCH];

// bf16 hi/lo operand buffers for tensor-core GEMMs
__device__ __nv_bfloat16 g_aw_h[QSZ],  g_aw_l[QSZ];   // [4096 win][6144 feat]
__device__ __nv_bfloat16 g_attg_h[(size_t)BATCH*NWIN*NWIN], g_attg_l[(size_t)BATCH*NWIN*NWIN];
__device__ __nv_bfloat16 g_w1h[(size_t)256*FEAT], g_w1l[(size_t)256*FEAT];

static __device__ __forceinline__ unsigned s2u(const void* p) {
    return (unsigned)__cvta_generic_to_shared(p);
}
static __device__ __forceinline__ void bf_split(float x, __nv_bfloat16& h, __nv_bfloat16& l) {
    h = __float2bfloat16(x);
    l = __float2bfloat16(x - __bfloat162float(h));
}
static __device__ __forceinline__ unsigned pack2(__nv_bfloat16 a, __nv_bfloat16 b) {
    return (unsigned)__bfloat16_as_ushort(a) | ((unsigned)__bfloat16_as_ushort(b) << 16);
}
static __device__ __forceinline__ void ldsm4(unsigned& r0, unsigned& r1, unsigned& r2, unsigned& r3, unsigned a) {
    asm volatile("ldmatrix.sync.aligned.m8n8.x4.shared.b16 {%0,%1,%2,%3}, [%4];"
        : "=r"(r0), "=r"(r1), "=r"(r2), "=r"(r3) : "r"(a));
}
static __device__ __forceinline__ void ldsm4t(unsigned& r0, unsigned& r1, unsigned& r2, unsigned& r3, unsigned a) {
    asm volatile("ldmatrix.sync.aligned.m8n8.x4.trans.shared.b16 {%0,%1,%2,%3}, [%4];"
        : "=r"(r0), "=r"(r1), "=r"(r2), "=r"(r3) : "r"(a));
}

#define MMA_BF16(cc, a0,a1,a2,a3, b0,b1) \
    asm volatile("mma.sync.aligned.m16n8k16.row.col.f32.bf16.bf16.f32 " \
        "{%0,%1,%2,%3}, {%4,%5,%6,%7}, {%8,%9}, {%0,%1,%2,%3};" \
        : "+f"(cc[0]), "+f"(cc[1]), "+f"(cc[2]), "+f"(cc[3]) \
        : "r"(a0), "r"(a1), "r"(a2), "r"(a3), "r"(b0), "r"(b1))

// ---------------- K0: zero the stat accumulators ----------------
__global__ void k_zero() {
    int t = threadIdx.x;
    if (t < BATCH) { g_ssum[t]=0.0; g_ssq[t]=0.0; g_csum[t]=0.0; g_csq[t]=0.0; }
}

// ---------------- K2: relative-position bias (6,64,64) ----------------
__global__ void k_bias(const float* __restrict__ m1, const float* __restrict__ b1,
                       const float* __restrict__ m2, const float* __restrict__ b2) {
    int n = blockIdx.x, m = threadIdx.x;            // 64 blocks x 64 threads
    int iyn = n >> 3, ixn = n & 7, iym = m >> 3, ixm = m & 7;
    float d0 = (float)(iyn - iym), d1 = (float)(ixn - ixm);
    float r0 = copysignf(log1pf(fabsf(d0)), d0);
    float r1 = copysignf(log1pf(fabsf(d1)), d1);
    float acc[NHEADS] = {0,0,0,0,0,0};
    for (int j = 0; j < 256; j++) {
        float h = fmaxf(m1[2*j]*r0 + m1[2*j+1]*r1 + b1[j], 0.f);
        #pragma unroll
        for (int hh = 0; hh < NHEADS; hh++) acc[hh] += h * m2[hh*256 + j];
    }
    for (int hh = 0; hh < NHEADS; hh++)
        g_bias[(hh*64 + n)*64 + m] = acc[hh] + b2[hh];
}

// ---------------- convert pe_w1 (256,6144) -> bf16 hi/lo (same layout) ----------------
__global__ void k_cvtw1(const float* __restrict__ w1) {
    size_t o = (size_t)blockIdx.x*256 + threadIdx.x;   // 6144 blocks
    float v = w1[o];
    __nv_bfloat16 h, l; bf_split(v, h, l);
    g_w1h[o] = h; g_w1l[o] = l;
}

// ---------------- K1: QKV 1x1 convs via tensor cores (bf16x3) ----------------
#define SXP 136   // Xs row stride (bf16 elems), padded for conflict-free ldmatrix
#define SWP 104   // Ws row stride
__global__ __launch_bounds__(256) void k_qkvmma(const float* __restrict__ X,
                                                const float* __restrict__ Qw,
                                                const float* __restrict__ Qb,
                                                const float* __restrict__ Vw,
                                                const float* __restrict__ Vb) {
    extern __shared__ __align__(16) __nv_bfloat16 smq[];
    __nv_bfloat16* Xh = smq;                 // 96 x SXP
    __nv_bfloat16* Xl = smq + 96*SXP;
    __nv_bfloat16* Wh = smq + 2*96*SXP;      // 96 x SWP
    __nv_bfloat16* Wl = Wh + 96*SWP;

    int t = threadIdx.x, lane = t & 31, wp = t >> 5;
    int base = blockIdx.x * 128;
    int b = base >> 16, y = (base >> 8) & 255, x0 = base & 255;

    // stage X tile (96 chans x 128 pixels), fp32 -> bf16 hi/lo
    const float* Xg = X + ((size_t)(b*96)*256 + y)*256 + x0;
    #pragma unroll
    for (int r = 0; r < 12; r++) {
        int i = t + 256*r;                  // 0..3071
        int c = i >> 5, p4 = i & 31;
        float4 v = *(const float4*)(Xg + (size_t)c*65536 + p4*4);
        __nv_bfloat16 h0,l0,h1,l1,h2,l2,h3,l3;
        bf_split(v.x,h0,l0); bf_split(v.y,h1,l1); bf_split(v.z,h2,l2); bf_split(v.w,h3,l3);
        *(uint2*)(Xh + c*SXP + p4*4) = make_uint2(pack2(h0,h1), pack2(h2,h3));
        *(uint2*)(Xl + c*SXP + p4*4) = make_uint2(pack2(l0,l1), pack2(l2,l3));
    }

    int wm = (wp >> 1)*32;         // 4 warp-rows of 32 pixels
    int wn = (wp & 1)*48;          // 2 warp-cols of 48 outs
    int wy = y >> 3, iy = y & 7;

    int a_k = (lane & 7) + ((lane >> 4) << 3);
    int a_m = ((lane >> 3) & 1) * 8;
    int b_n = (lane & 7) + ((lane >> 4) << 3);
    int b_k = ((lane >> 3) & 1) * 8;

    for (int ch = 0; ch < 3; ch++) {
        if (ch) __syncthreads();
        const float* Wg = (ch == 2) ? Vw : (Qw + ch*96*96);
        #pragma unroll
        for (int r = 0; r < 9; r++) {
            int i = t + 256*r;              // 0..2303
            int row = i / 24, c4 = i % 24;
            float4 v = *(const float4*)(Wg + row*96 + c4*4);
            __nv_bfloat16 h0,l0,h1,l1,h2,l2,h3,l3;
            bf_split(v.x,h0,l0); bf_split(v.y,h1,l1); bf_split(v.z,h2,l2); bf_split(v.w,h3,l3);
            *(uint2*)(Wh + row*SWP + c4*4) = make_uint2(pack2(h0,h1), pack2(h2,h3));
            *(uint2*)(Wl + row*SWP + c4*4) = make_uint2(pack2(l0,l1), pack2(l2,l3));
        }
        __syncthreads();

        float acc[2][6][4] = {};
        #pragma unroll
        for (int ks = 0; ks < 6; ks++) {
            int k0 = ks*16;
            unsigned ah[2][4], al[2][4];
            #pragma unroll
            for (int mt = 0; mt < 2; mt++) {
                int m0 = wm + mt*16 + a_m;
                ldsm4t(ah[mt][0], ah[mt][1], ah[mt][2], ah[mt][3],
                       s2u(Xh + (k0 + a_k)*SXP + m0));
                ldsm4t(al[mt][0], al[mt][1], al[mt][2], al[mt][3],
                       s2u(Xl + (k0 + a_k)*SXP + m0));
            }
            unsigned bh[6][2], bl[6][2];
            #pragma unroll
            for (int bj = 0; bj < 3; bj++) {
                int nb = wn + bj*16 + b_n;
                unsigned r0,r1,r2,r3;
                ldsm4(r0,r1,r2,r3, s2u(Wh + nb*SWP + k0 + b_k));
                bh[2*bj][0]=r0; bh[2*bj][1]=r1; bh[2*bj+1][0]=r2; bh[2*bj+1][1]=r3;
                ldsm4(r0,r1,r2,r3, s2u(Wl + nb*SWP + k0 + b_k));
                bl[2*bj][0]=r0; bl[2*bj][1]=r1; bl[2*bj+1][0]=r2; bl[2*bj+1][1]=r3;
            }
            #pragma unroll
            for (int mt = 0; mt < 2; mt++)
                #pragma unroll
                for (int nt = 0; nt < 6; nt++) {
                    MMA_BF16(acc[mt][nt], ah[mt][0],ah[mt][1],ah[mt][2],ah[mt][3], bh[nt][0],bh[nt][1]);
                    MMA_BF16(acc[mt][nt], ah[mt][0],ah[mt][1],ah[mt][2],ah[mt][3], bl[nt][0],bl[nt][1]);
                    MMA_BF16(acc[mt][nt], al[mt][0],al[mt][1],al[mt][2],al[mt][3], bh[nt][0],bh[nt][1]);
                }
        }

        const float* bias = (ch == 2) ? Vb : (Qb + ch*96);
        float scl = (ch == 0) ? 0.25f : 1.f;
        float* dst = (ch == 0) ? g_q : (ch == 1) ? g_k : g_v;
        #pragma unroll
        for (int mt = 0; mt < 2; mt++) {
            #pragma unroll
            for (int half = 0; half < 2; half++) {
                int m = wm + mt*16 + (lane >> 2) + half*8;
                int x = x0 + m; int wx = x >> 3, ix = x & 7;
                size_t woff = ((size_t)((b*32 + wy)*32 + wx)*64 + iy*8 + ix)*96;
                #pragma unroll
                for (int nt = 0; nt < 6; nt++) {
                    int d = wn + nt*8 + (lane & 3)*2;
                    float v0 = (acc[mt][nt][half*2 + 0] + bias[d])   * scl;
                    float v1 = (acc[mt][nt][half*2 + 1] + bias[d+1]) * scl;
                    *(float2*)(dst + woff + d) = make_float2(v0, v1);
                }
            }
        }
    }
}

// ---------------- K3: window attention (two-pass softmax; no serial rescale) ----------------
__global__ void k_attn() {
    __shared__ __align__(16) float sm[2*FEAT];      // 48KB: K tile, V tile
    float* Ks = sm; float* Vs = sm + FEAT;
    int w = blockIdx.x; int tid = threadIdx.x;      // 384 threads
    int b = w >> 10;
    const float4* kg = (const float4*)(g_k + (size_t)w*FEAT);
    const float4* vg = (const float4*)(g_v + (size_t)w*FEAT);
    #pragma unroll
    for (int i = tid; i < FEAT/4; i += 384) { ((float4*)Ks)[i] = kg[i]; ((float4*)Vs)[i] = vg[i]; }
    int h = tid / 64, n = tid & 63;
    float q[HD];
    const float* qg = g_q + ((size_t)w*NTOK + n)*CH + h*HD;
    #pragma unroll
    for (int d4 = 0; d4 < 4; d4++) *(float4*)(q + d4*4) = *(const float4*)(qg + d4*4);
    __syncthreads();
    const float* bs = g_bias + (h*64 + n)*64;

    // pass A: global max over all 64 scores (independent dot groups, fmaxf trees)
    float mxa = -1e30f, mxb = -1e30f;
    for (int m = 0; m < 64; m += 4) {
        float s[4];
        #pragma unroll
        for (int j = 0; j < 4; j++) {
            const float4* kr = (const float4*)(Ks + (m + j)*CH + h*HD);
            float ss = bs[m + j];
            #pragma unroll
            for (int d4 = 0; d4 < 4; d4++) {
                float4 kv = kr[d4];
                ss += q[d4*4]*kv.x + q[d4*4+1]*kv.y + q[d4*4+2]*kv.z + q[d4*4+3]*kv.w;
            }
            s[j] = ss;
        }
        mxa = fmaxf(mxa, fmaxf(s[0], s[1]));
        mxb = fmaxf(mxb, fmaxf(s[2], s[3]));
    }
    float mx = fmaxf(mxa, mxb);

    // pass B: recompute scores, exp with known max, accumulate (no corr chain)
    float l = 0.f, o[HD];
    #pragma unroll
    for (int d = 0; d < HD; d++) o[d] = 0.f;
    for (int m = 0; m < 64; m += 4) {
        float s[4];
        #pragma unroll
        for (int j = 0; j < 4; j++) {
            const float4* kr = (const float4*)(Ks + (m + j)*CH + h*HD);
            float ss = bs[m + j];
            #pragma unroll
            for (int d4 = 0; d4 < 4; d4++) {
                float4 kv = kr[d4];
                ss += q[d4*4]*kv.x + q[d4*4+1]*kv.y + q[d4*4+2]*kv.z + q[d4*4+3]*kv.w;
            }
            s[j] = ss;
        }
        float p0 = __expf(s[0] - mx);
        float p1 = __expf(s[1] - mx);
        float p2 = __expf(s[2] - mx);
        float p3 = __expf(s[3] - mx);
        l += (p0 + p1) + (p2 + p3);
        const float4* vr0 = (const float4*)(Vs + m*CH + h*HD);
        const float4* vr1 = (const float4*)(Vs + (m+1)*CH + h*HD);
        const float4* vr2 = (const float4*)(Vs + (m+2)*CH + h*HD);
        const float4* vr3 = (const float4*)(Vs + (m+3)*CH + h*HD);
        #pragma unroll
        for (int d4 = 0; d4 < 4; d4++) {
            float4 v0 = vr0[d4], v1 = vr1[d4], v2 = vr2[d4], v3 = vr3[d4];
            o[d4*4]   += (p0*v0.x + p1*v1.x) + (p2*v2.x + p3*v3.x);
            o[d4*4+1] += (p0*v0.y + p1*v1.y) + (p2*v2.y + p3*v3.y);
            o[d4*4+2] += (p0*v0.z + p1*v1.z) + (p2*v2.z + p3*v3.z);
            o[d4*4+3] += (p0*v0.w + p1*v1.w) + (p2*v2.w + p3*v3.w);
        }
    }
    float inv = 1.f / l;
    size_t oidx = ((size_t)w*NTOK + n)*CH + h*HD;
    float ls = 0.f, lq = 0.f;
    #pragma unroll
    for (int d = 0; d < HD; d++) {
        float vv = o[d]*inv; ls += vv; lq += vv*vv;
        __nv_bfloat16 bh, bl; bf_split(vv, bh, bl);
        g_aw_h[oidx + d] = bh; g_aw_l[oidx + d] = bl;
    }
    double ds = ls, dq = lq;
    for (int off = 16; off; off >>= 1) {
        ds += __shfl_down_sync(0xffffffffu, ds, off);
        dq += __shfl_down_sync(0xffffffffu, dq, off);
    }
    __syncthreads();                                 // all Ks/Vs reads done
    double* red = (double*)sm;
    int wid = tid >> 5, lane = tid & 31;
    if (lane == 0) { red[wid] = ds; red[12 + wid] = dq; }
    __syncthreads();
    if (tid == 0) {
        double a = 0, c = 0;
        for (int i = 0; i < 12; i++) { a += red[i]; c += red[12 + i]; }
        atomicAdd(&g_ssum[b], a); atomicAdd(&g_ssq[b], c);
    }
}

// ---------------- tensor-core GEMM (bf16x3) with ldmatrix fragments ----------------
// MODE 0: split-K partials of (aw @ w1^T) -> g_Hp[z]   (B [n][k], non-trans ldsm)
// MODE 1: rw = (attg @ aw)*scale + shift               (B [k][n], trans ldsm)
template<int MODE>
__global__ __launch_bounds__(256, 2) void k_tcgemm(const float* __restrict__ bias) {
    constexpr int K    = (MODE == 0) ? FEAT : NWIN;
    constexpr int Ndim = (MODE == 0) ? 256  : FEAT;
    constexpr int ASZ  = 128*40;
    constexpr int BSZ  = (MODE == 0) ? 128*40 : 32*136;
    extern __shared__ __align__(16) __nv_bfloat16 smbuf[];
    __nv_bfloat16* Ab = smbuf;            // [stage*2+hl][ASZ]
    __nv_bfloat16* Bb = smbuf + 4*ASZ;    // [stage*2+hl][BSZ]

    const __nv_bfloat16 *Ah, *Al, *Bh, *Bl;
    float* C;
    if (MODE == 0) {
        Ah = g_aw_h; Al = g_aw_l; Bh = g_w1h; Bl = g_w1l;
        C = g_Hp + (size_t)blockIdx.z*NWTOT*256;
    } else {
        size_t z = blockIdx.z;
        Ah = g_attg_h + z*NWIN*NWIN; Al = g_attg_l + z*NWIN*NWIN;
        Bh = g_aw_h + z*NWIN*FEAT;  Bl = g_aw_l + z*NWIN*FEAT;
        C  = g_rw   + z*NWIN*FEAT;
    }
    int m0 = blockIdx.y*128, n0 = blockIdx.x*128;
    int t = threadIdx.x;

#define LOAD_STAGE(st, kb) { \
    int arr = t >> 6, tt = t & 63; \
    if (arr < 2) { \
        const __nv_bfloat16* g = arr ? Al : Ah; \
        _Pragma("unroll") \
        for (int rr = 0; rr < 2; rr++) { \
            int r = tt*2 + rr; \
            const __nv_bfloat16* src = g + (size_t)(m0 + r)*K + (kb); \
            unsigned dstb = s2u(Ab + ((st)*2+arr)*ASZ + r*40); \
            _Pragma("unroll") \
            for (int seg = 0; seg < 4; seg++) \
                asm volatile("cp.async.cg.shared.global [%0], [%1], 16;" \
                    :: "r"(dstb + seg*16), "l"(src + seg*8)); \
        } \
    } else { \
        int hl = arr - 2; \
        const __nv_bfloat16* g = hl ? Bl : Bh; \
        if (MODE == 0) { \
            _Pragma("unroll") \
            for (int rr = 0; rr < 2; rr++) { \
                int r = tt*2 + rr; \
                const __nv_bfloat16* src = g + (size_t)(n0 + r)*K + (kb); \
                unsigned dstb = s2u(Bb + ((st)*2+hl)*BSZ + r*40); \
                _Pragma("unroll") \
                for (int seg = 0; seg < 4; seg++) \
                    asm volatile("cp.async.cg.shared.global [%0], [%1], 16;" \
                        :: "r"(dstb + seg*16), "l"(src + seg*8)); \
            } \
        } else { \
            _Pragma("unroll") \
            for (int j = 0; j < 8; j++) { \
                int idx = tt*8 + j; \
                int row = idx >> 4, col = idx & 15; \
                const __nv_bfloat16* src = g + (size_t)((kb) + row)*FEAT + n0 + col*8; \
                unsigned dstb = s2u(Bb + ((st)*2+hl)*BSZ + row*136 + col*8); \
                asm volatile("cp.async.cg.shared.global [%0], [%1], 16;" \
                    :: "r"(dstb), "l"(src)); \
            } \
        } \
    } \
    asm volatile("cp.async.commit_group;"); }

    float acc[4][4][4];
    #pragma unroll
    for (int i = 0; i < 4; i++)
        #pragma unroll
        for (int j = 0; j < 4; j++)
            #pragma unroll
            for (int q = 0; q < 4; q++) acc[i][j][q] = 0.f;

    int lane = t & 31, wp = t >> 5;
    int wm = (wp >> 2)*64, wn = (wp & 3)*32;

    // fragment lane addressing (verified mappings)
    int a_m = lane & 15, a_k = (lane >> 4)*8;                       // A non-trans
    int b_n = (lane & 7) + ((lane >> 4) << 3), b_k = ((lane >> 3) & 1)*8;   // B non-trans [n][k]
    int tb_k = (lane & 7) + ((lane >> 3) & 1)*8, tb_n = (lane >> 4)*8;      // B trans [k][n]

    constexpr int NK = (MODE == 0) ? (FEAT/4)/32 : K/32;
    int koff = (MODE == 0) ? blockIdx.z*(FEAT/4) : 0;
    LOAD_STAGE(0, koff);
    for (int c = 0; c < NK; c++) {
        if (c + 1 < NK) {
            LOAD_STAGE((c+1)&1, koff + (c+1)*32);
            asm volatile("cp.async.wait_group 1;");
        } else {
            asm volatile("cp.async.wait_group 0;");
        }
        __syncthreads();
        int st = c & 1;
        const __nv_bfloat16* sah = Ab + (st*2+0)*ASZ;
        const __nv_bfloat16* sal = Ab + (st*2+1)*ASZ;
        const __nv_bfloat16* sbh = Bb + (st*2+0)*BSZ;
        const __nv_bfloat16* sbl = Bb + (st*2+1)*BSZ;
        #pragma unroll
        for (int ks = 0; ks < 2; ks++) {
            unsigned ah[4][4], bh[4][2], bl[4][2];
            #pragma unroll
            for (int i = 0; i < 4; i++)
                ldsm4(ah[i][0], ah[i][1], ah[i][2], ah[i][3],
                      s2u(sah + (wm + i*16 + a_m)*40 + ks*16 + a_k));
            if (MODE == 0) {
                #pragma unroll
                for (int bj = 0; bj < 2; bj++) {
                    unsigned r0,r1,r2,r3;
                    ldsm4(r0,r1,r2,r3, s2u(sbh + (wn + bj*16 + b_n)*40 + ks*16 + b_k));
                    bh[2*bj][0]=r0; bh[2*bj][1]=r1; bh[2*bj+1][0]=r2; bh[2*bj+1][1]=r3;
                    ldsm4(r0,r1,r2,r3, s2u(sbl + (wn + bj*16 + b_n)*40 + ks*16 + b_k));
                    bl[2*bj][0]=r0; bl[2*bj][1]=r1; bl[2*bj+1][0]=r2; bl[2*bj+1][1]=r3;
                }
            } else {
                #pragma unroll
                for (int bj = 0; bj < 2; bj++) {
                    unsigned r0,r1,r2,r3;
                    ldsm4t(r0,r1,r2,r3, s2u(sbh + (ks*16 + tb_k)*136 + wn + bj*16 + tb_n));
                    bh[2*bj][0]=r0; bh[2*bj][1]=r1; bh[2*bj+1][0]=r2; bh[2*bj+1][1]=r3;
                    ldsm4t(r0,r1,r2,r3, s2u(sbl + (ks*16 + tb_k)*136 + wn + bj*16 + tb_n));
                    bl[2*bj][0]=r0; bl[2*bj][1]=r1; bl[2*bj+1][0]=r2; bl[2*bj+1][1]=r3;
                }
            }
            // pass 1+2: hi*hi, hi*lo
            #pragma unroll
            for (int j = 0; j < 4; j++)
                #pragma unroll
                for (int i = 0; i < 4; i++) {
                    MMA_BF16(acc[i][j], ah[i][0], ah[i][1], ah[i][2], ah[i][3], bh[j][0], bh[j][1]);
                    MMA_BF16(acc[i][j], ah[i][0], ah[i][1], ah[i][2], ah[i][3], bl[j][0], bl[j][1]);
                }
            // pass 3: lo*hi (load al after ah is dead)
            unsigned al[4][4];
            #pragma unroll
            for (int i = 0; i < 4; i++)
                ldsm4(al[i][0], al[i][1], al[i][2], al[i][3],
                      s2u(sal + (wm + i*16 + a_m)*40 + ks*16 + a_k));
            #pragma unroll
            for (int j = 0; j < 4; j++)
                #pragma unroll
                for (int i = 0; i < 4; i++)
                    MMA_BF16(acc[i][j], al[i][0], al[i][1], al[i][2], al[i][3], bh[j][0], bh[j][1]);
        }
        __syncthreads();
    }

    float gsc = 1.f, gof = 0.f;
    if (MODE == 1) { gsc = g_scale[blockIdx.z]; gof = g_shift[blockIdx.z]; }
    #pragma unroll
    for (int i = 0; i < 4; i++) {
        int row = m0 + wm + i*16 + (lane >> 2);
        #pragma unroll
        for (int j = 0; j < 4; j++) {
            int col = n0 + wn + j*8 + (lane & 3)*2;
            float* cc = acc[i][j];
            if (MODE == 0) {
                // raw split-K partials (bias+relu applied in k_redH)
                *(float2*)(C + (size_t)row*Ndim + col)     = make_float2(cc[0], cc[1]);
                *(float2*)(C + (size_t)(row+8)*Ndim + col) = make_float2(cc[2], cc[3]);
            } else {
                float2 v0 = make_float2(cc[0]*gsc+gof, cc[1]*gsc+gof);
                float2 v1 = make_float2(cc[2]*gsc+gof, cc[3]*gsc+gof);
                *(float2*)(C + (size_t)row*Ndim + col)     = v0;
                *(float2*)(C + (size_t)(row+8)*Ndim + col) = v1;
            }
        }
    }
#undef LOAD_STAGE
}

// ---------------- reduce split-K partials: H = relu(sum_z Hp[z] + b1) ----------------
__global__ void k_redH(const float* __restrict__ b1v) {
    size_t o = (size_t)blockIdx.x*256 + threadIdx.x;    // 4096 blocks x 256 thr
    const size_t STRIDE = (size_t)NWTOT*256;
    float s = g_Hp[o] + g_Hp[o + STRIDE] + g_Hp[o + 2*STRIDE] + g_Hp[o + 3*STRIDE];
    g_H[o] = fmaxf(s + b1v[threadIdx.x], 0.f);
}

// ---------------- K4b: emb = l2norm(H @ pe_w2^T + b2) -> embT + cur stats ----------------
__global__ void k_emb(const float* __restrict__ w2, const float* __restrict__ b2) {
    __shared__ float hs[256];
    int w = blockIdx.x; int t = threadIdx.x;        // 32 threads
    const float* hr = g_H + (size_t)w*256;
    for (int i = t; i < 256; i += 32) hs[i] = hr[i];
    __syncwarp();
    float e = 0.f;
    if (t < PDIM) {
        e = b2[t];
        const float* wr = w2 + t*256;
        for (int j = 0; j < 256; j++) e += hs[j]*wr[j];
    }
    float sq = e*e;
    for (int off = 16; off; off >>= 1) sq += __shfl_down_sync(0xffffffffu, sq, off);
    sq = __shfl_sync(0xffffffffu, sq, 0);
    float inv = 1.f / (sqrtf(sq) + EPSV);
    e *= inv;
    if (t < PDIM) g_embT[(size_t)t*NWTOT + w] = e;
    double d1 = (t < PDIM) ? (double)e : 0.0;
    double d2 = (t < PDIM) ? (double)(e*e) : 0.0;
    for (int off = 16; off; off >>= 1) {
        d1 += __shfl_down_sync(0xffffffffu, d1, off);
        d2 += __shfl_down_sync(0xffffffffu, d2, off);
    }
    if (t == 0) { int b = w >> 10; atomicAdd(&g_csum[b], d1); atomicAdd(&g_csq[b], d2); }
}

// ---------------- finalize per-batch affine (scale/shift) ----------------
__global__ void k_fin() {
    int b = threadIdx.x; if (b >= BATCH) return;
    double ns = (double)NWIN * FEAT;
    double sm = g_ssum[b]/ns, sv = g_ssq[b]/ns - sm*sm;
    float sstd = sqrtf((float)sv + EPSV);
    double nc = (double)NWIN * PDIM;
    double cm = g_csum[b]/nc, cv = g_csq[b]/nc - cm*cm;
    float cstd = sqrtf((float)cv + EPSV);
    float g = sstd / cstd;
    g_scale[b] = g;
    g_shift[b] = (float)sm - (float)cm * g;
}

// ---------------- K5: att_g = l1norm(exp(a*emb@emb^T + c)) -> bf16 hi/lo ----------------
__global__ void k_attg(const float* __restrict__ alpha, const float* __restrict__ beta) {
    __shared__ float en[PDIM];
    __shared__ float red[256];
    int b = blockIdx.y, n = blockIdx.x, t = threadIdx.x;  // 256 threads
    if (t < PDIM) en[t] = g_embT[(size_t)t*NWTOT + b*NWIN + n];
    __syncthreads();
    float a = 30.f * alpha[0], c = 20.f * beta[0];
    float v[4]; float s = 0.f;
    #pragma unroll
    for (int r = 0; r < 4; r++) {
        int m = t + r*256;
        float d = 0.f;
        #pragma unroll
        for (int j = 0; j < PDIM; j++)
            d += en[j] * g_embT[(size_t)j*NWTOT + b*NWIN + m];
        float ev = __expf(a*d + c);
        v[r] = ev; s += ev;
    }
    red[t] = s; __syncthreads();
    for (int off = 128; off; off >>= 1) { if (t < off) red[t] += red[t + off]; __syncthreads(); }
    float inv = 1.f / (red[0] + EPSV);
    size_t rbase = ((size_t)(b*NWIN + n))*NWIN;
    #pragma unroll
    for (int r = 0; r < 4; r++) {
        float vv = v[r]*inv;
        __nv_bfloat16 bh, bl; bf_split(vv, bh, bl);
        g_attg_h[rbase + t + r*256] = bh;
        g_attg_l[rbase + t + r*256] = bl;
    }
}

// ---------------- K7: depthwise 5x5 (reflect) + window-reverse gather -> S ----------------
#define CVP 145
__global__ __launch_bounds__(384) void k_conv(const float* __restrict__ dww,
                                              const float* __restrict__ dwb) {
    __shared__ float sv[48*CVP];                     // 48 channels x 12x12 halo (padded)
    __shared__ float sw[48*25];
    int blk = blockIdx.x; int w = blk >> 1, half = blk & 1;
    int b = w >> 10, wy = (w >> 5) & 31, wx = w & 31;
    int y0 = wy*8, x0 = wx*8;
    int t = threadIdx.x;                             // 384 threads
    for (int i = t; i < 48*25; i += 384) sw[i] = dww[half*48*25 + i];
    for (int i = t; i < 48*144; i += 384) {
        int cl = i % 48, pidx = i / 48;
        int gy = y0 - 2 + pidx/12, gx = x0 - 2 + pidx%12;
        gy = gy < 0 ? -gy : (gy > 255 ? 510 - gy : gy);
        gx = gx < 0 ? -gx : (gx > 255 ? 510 - gx : gx);
        int wyp = gy >> 3, wxp = gx >> 3, widx = (gy & 7)*8 + (gx & 7);
        sv[cl*CVP + pidx] =
            g_v[(((size_t)((b*32 + wyp)*32 + wxp))*64 + widx)*96 + half*48 + cl];
    }
    __syncthreads();
    int c = t % 48, g = t / 48;                      // channel, window row
    int cg = half*48 + c;
    float wreg[25];
    #pragma unroll
    for (int k2 = 0; k2 < 25; k2++) wreg[k2] = sw[c*25 + k2];
    float acc[8];
    float bb = dwb[cg];
    #pragma unroll
    for (int ix = 0; ix < 8; ix++) acc[ix] = bb;
    const float* svc = sv + c*CVP;
    #pragma unroll
    for (int ky = 0; ky < 5; ky++) {
        float row[12];
        #pragma unroll
        for (int xx = 0; xx < 12; xx++) row[xx] = svc[(g + ky)*12 + xx];
        #pragma unroll
        for (int kx = 0; kx < 5; kx++) {
            float wv = wreg[ky*5 + kx];
            #pragma unroll
            for (int ix = 0; ix < 8; ix++) acc[ix] += wv*row[ix + kx];
        }
    }
    const float* rwb = g_rw + (size_t)w*FEAT;
    #pragma unroll
    for (int ix = 0; ix < 8; ix++) {
        int pix = g*8 + ix;
        g_S[((size_t)(b*IMG + y0 + g)*IMG + x0 + ix)*CH + cg] = acc[ix] + rwb[pix*CH + cg];
    }
}

// ---------------- K8: out = proj(S) + proj_b via tensor cores (bf16x3) ----------------
#define SSP 104   // Ss row stride
#define OSP 136   // Os row stride (fp32)
__global__ __launch_bounds__(256) void k_projmma(const float* __restrict__ pw,
                                                 const float* __restrict__ pb,
                                                 float* __restrict__ out) {
    extern __shared__ __align__(16) __nv_bfloat16 smp[];
    __nv_bfloat16* Sh = smp;                 // 128 x SSP
    __nv_bfloat16* Sl = smp + 128*SSP;
    __nv_bfloat16* Wh = smp + 2*128*SSP;     // 96 x SSP
    __nv_bfloat16* Wl = Wh + 96*SSP;
    float* Os = (float*)smp;                 // aliased after compute: 96 x OSP

    int t = threadIdx.x, lane = t & 31, wp = t >> 5;
    int base = blockIdx.x * 128;
    int b = base >> 16, y = (base >> 8) & 255, x0 = base & 255;

    const float* Sg = g_S + (size_t)base*96;
    #pragma unroll
    for (int r = 0; r < 12; r++) {
        int i = t + 256*r;
        int row = i / 24, c4 = i % 24;
        float4 v = *(const float4*)(Sg + (size_t)row*96 + c4*4);
        __nv_bfloat16 h0,l0,h1,l1,h2,l2,h3,l3;
        bf_split(v.x,h0,l0); bf_split(v.y,h1,l1); bf_split(v.z,h2,l2); bf_split(v.w,h3,l3);
        *(uint2*)(Sh + row*SSP + c4*4) = make_uint2(pack2(h0,h1), pack2(h2,h3));
        *(uint2*)(Sl + row*SSP + c4*4) = make_uint2(pack2(l0,l1), pack2(l2,l3));
    }
    #pragma unroll
    for (int r = 0; r < 9; r++) {
        int i = t + 256*r;
        int row = i / 24, c4 = i % 24;
        float4 v = *(const float4*)(pw + row*96 + c4*4);
        __nv_bfloat16 h0,l0,h1,l1,h2,l2,h3,l3;
        bf_split(v.x,h0,l0); bf_split(v.y,h1,l1); bf_split(v.z,h2,l2); bf_split(v.w,h3,l3);
        *(uint2*)(Wh + row*SSP + c4*4) = make_uint2(pack2(h0,h1), pack2(h2,h3));
        *(uint2*)(Wl + row*SSP + c4*4) = make_uint2(pack2(l0,l1), pack2(l2,l3));
    }
    __syncthreads();

    int wm = (wp >> 1)*32, wn = (wp & 1)*48;
    int a_m = (lane & 7) + ((lane >> 3) & 1)*8;
    int a_k = (lane >> 4)*8;
    int b_n = (lane & 7) + ((lane >> 4) << 3);
    int b_k = ((lane >> 3) & 1)*8;

    float acc[2][6][4] = {};
    #pragma unroll
    for (int ks = 0; ks < 6; ks++) {
        int k0 = ks*16;
        unsigned ah[2][4], al[2][4];
        #pragma unroll
        for (int mt = 0; mt < 2; mt++) {
            int m0 = wm + mt*16 + a_m;
            ldsm4(ah[mt][0], ah[mt][1], ah[mt][2], ah[mt][3], s2u(Sh + m0*SSP + k0 + a_k));
            ldsm4(al[mt][0], al[mt][1], al[mt][2], al[mt][3], s2u(Sl + m0*SSP + k0 + a_k));
        }
        unsigned bh[6][2], bl[6][2];
        #pragma unroll
        for (int bj = 0; bj < 3; bj++) {
            int nb = wn + bj*16 + b_n;
            unsigned r0,r1,r2,r3;
            ldsm4(r0,r1,r2,r3, s2u(Wh + nb*SSP + k0 + b_k));
            bh[2*bj][0]=r0; bh[2*bj][1]=r1; bh[2*bj+1][0]=r2; bh[2*bj+1][1]=r3;
            ldsm4(r0,r1,r2,r3, s2u(Wl + nb*SSP + k0 + b_k));
            bl[2*bj][0]=r0; bl[2*bj][1]=r1; bl[2*bj+1][0]=r2; bl[2*bj+1][1]=r3;
        }
        #pragma unroll
        for (int mt = 0; mt < 2; mt++)
            #pragma unroll
            for (int nt = 0; nt < 6; nt++) {
                MMA_BF16(acc[mt][nt], ah[mt][0],ah[mt][1],ah[mt][2],ah[mt][3], bh[nt][0],bh[nt][1]);
                MMA_BF16(acc[mt][nt], ah[mt][0],ah[mt][1],ah[mt][2],ah[mt][3], bl[nt][0],bl[nt][1]);
                MMA_BF16(acc[mt][nt], al[mt][0],al[mt][1],al[mt][2],al[mt][3], bh[nt][0],bh[nt][1]);
            }
    }
    __syncthreads();
    #pragma unroll
    for (int mt = 0; mt < 2; mt++)
        #pragma unroll
        for (int half = 0; half < 2; half++) {
            int m = wm + mt*16 + (lane >> 2) + half*8;
            #pragma unroll
            for (int nt = 0; nt < 6; nt++) {
                int d = wn + nt*8 + (lane & 3)*2;
                Os[d*OSP + m]     = acc[mt][nt][half*2 + 0];
                Os[(d+1)*OSP + m] = acc[mt][nt][half*2 + 1];
            }
        }
    __syncthreads();
    #pragma unroll
    for (int r = 0; r < 12; r++) {
        int i = t + 256*r;
        int d = i >> 5, p4 = i & 31;
        float4 v = *(const float4*)(Os + d*OSP + p4*4);
        float bb = pb[d];
        v.x += bb; v.y += bb; v.z += bb; v.w += bb;
        *(float4*)(out + ((size_t)(b*96 + d))*65536 + y*256 + x0 + p4*4) = v;
    }
}

// ---------------- host ----------------
extern "C" void kernel_launch(void* const* d_in, const int* in_sizes, int n_in,
                              void* d_out, int out_size) {
    const float* X     = (const float*)d_in[0];
    const float* V_w   = (const float*)d_in[1];
    const float* V_b   = (const float*)d_in[2];
    const float* QK_w  = (const float*)d_in[3];
    const float* QK_b  = (const float*)d_in[4];
    const float* proj_w= (const float*)d_in[5];
    const float* proj_b= (const float*)d_in[6];
    const float* dw_w  = (const float*)d_in[7];
    const float* dw_b  = (const float*)d_in[8];
    const float* m_w1  = (const float*)d_in[9];
    const float* m_b1  = (const float*)d_in[10];
    const float* m_w2  = (const float*)d_in[11];
    const float* m_b2  = (const float*)d_in[12];
    const float* pe_w1 = (const float*)d_in[13];
    const float* pe_b1 = (const float*)d_in[14];
    const float* pe_w2 = (const float*)d_in[15];
    const float* pe_b2 = (const float*)d_in[16];
    const float* a_al  = (const float*)d_in[17];
    const float* a_be  = (const float*)d_in[18];
    float* out = (float*)d_out;

    const int TCSMEM0  = (4*128*40 + 4*128*40)*2;         // 81920 bytes
    const int TCSMEM1  = (4*128*40 + 4*32*136)*2;         // 75776 bytes
    const int QKVSMEM  = (2*96*SXP + 2*96*SWP)*2;         // 92160 bytes
    const int PROJSMEM = (2*128*SSP + 2*96*SSP)*2;        // 93184 bytes
    cudaFuncSetAttribute(k_tcgemm<0>, cudaFuncAttributeMaxDynamicSharedMemorySize, TCSMEM0);
    cudaFuncSetAttribute(k_tcgemm<1>, cudaFuncAttributeMaxDynamicSharedMemorySize, TCSMEM1);
    cudaFuncSetAttribute(k_qkvmma,    cudaFuncAttributeMaxDynamicSharedMemorySize, QKVSMEM);
    cudaFuncSetAttribute(k_projmma,   cudaFuncAttributeMaxDynamicSharedMemorySize, PROJSMEM);

    // launch order: k_attn at slot 4 (= the ncu capture slot) to verify the fix
    k_qkvmma<<<NPIX/128, 256, QKVSMEM>>>(X, QK_w, QK_b, V_w, V_b);   // 1
    k_bias<<<64, 64>>>(m_w1, m_b1, m_w2, m_b2);                      // 2
    k_zero<<<1, 32>>>();                                             // 3
    k_attn<<<NWTOT, 384>>>();                                        // 4 <- profiled
    k_cvtw1<<<6144, 256>>>(pe_w1);                                   // 5
    k_tcgemm<0><<<dim3(2, 32, 4), 256, TCSMEM0>>>(nullptr);          // split-K partials
    k_redH<<<NWTOT, 256>>>(pe_b1);                                   // H = relu(sum + b1)
    k_emb<<<NWTOT, 32>>>(pe_w2, pe_b2);
    k_fin<<<1, 32>>>();
    k_attg<<<dim3(NWIN, BATCH), 256>>>(a_al, a_be);
    k_tcgemm<1><<<dim3(FEAT/128, NWIN/128, BATCH), 256, TCSMEM1>>>(nullptr); // rw
    k_conv<<<NWTOT*2, 384>>>(dw_w, dw_b);
    k_projmma<<<NPIX/128, 256, PROJSMEM>>>(proj_w, proj_b, out);
}

// round 17
// speedup vs baseline: 1.1894x; 1.1894x over previous
#include <cuda_runtime.h>
#include <cuda_bf16.h>
#include <math.h>

#define BATCH 4
#define CH 96
#define IMG 256
#define WSZ 8
#define NWIN 1024          // 32x32 windows per image
#define NTOK 64
#define NHEADS 6
#define HD 16
#define PDIM 30
#define EPSV 1e-8f
#define NPIX (BATCH*IMG*IMG)        // 262144
#define NWTOT (BATCH*NWIN)          // 4096
#define FEAT (NTOK*CH)              // 6144
#define QSZ ((size_t)NWTOT*NTOK*CH) // 25165824

// ---------------- scratch (static device globals; no allocation) ----------------
__device__ float g_q[QSZ];       // later: S = conv_out + attn_out (pixel-major)
__device__ float g_k[QSZ];       // later: rw (global-attention output)
__device__ float g_v[QSZ];
#define g_S  g_q
#define g_rw g_k
__device__ float g_H[(size_t)NWTOT*256];
__device__ float g_Hp[(size_t)4*NWTOT*256];      // split-K partials for gemm1
__device__ float g_embT[(size_t)PDIM*NWTOT];     // transposed: [PDIM][NWTOT]
__device__ float g_bias[NHEADS*NTOK*NTOK];
__device__ double g_ssum[BATCH], g_ssq[BATCH], g_csum[BATCH], g_csq[BATCH];
__device__ float g_scale[BATCH], g_shift[BATCH];

// bf16 hi/lo operand buffers for tensor-core GEMMs
__device__ __nv_bfloat16 g_aw_h[QSZ],  g_aw_l[QSZ];   // [4096 win][6144 feat]
__device__ __nv_bfloat16 g_attg_h[(size_t)BATCH*NWIN*NWIN], g_attg_l[(size_t)BATCH*NWIN*NWIN];
__device__ __nv_bfloat16 g_w1h[(size_t)256*FEAT], g_w1l[(size_t)256*FEAT];

static __device__ __forceinline__ unsigned s2u(const void* p) {
    return (unsigned)__cvta_generic_to_shared(p);
}
static __device__ __forceinline__ void bf_split(float x, __nv_bfloat16& h, __nv_bfloat16& l) {
    h = __float2bfloat16(x);
    l = __float2bfloat16(x - __bfloat162float(h));
}
static __device__ __forceinline__ unsigned pack2(__nv_bfloat16 a, __nv_bfloat16 b) {
    return (unsigned)__bfloat16_as_ushort(a) | ((unsigned)__bfloat16_as_ushort(b) << 16);
}
static __device__ __forceinline__ void ldsm4(unsigned& r0, unsigned& r1, unsigned& r2, unsigned& r3, unsigned a) {
    asm volatile("ldmatrix.sync.aligned.m8n8.x4.shared.b16 {%0,%1,%2,%3}, [%4];"
        : "=r"(r0), "=r"(r1), "=r"(r2), "=r"(r3) : "r"(a));
}
static __device__ __forceinline__ void ldsm4t(unsigned& r0, unsigned& r1, unsigned& r2, unsigned& r3, unsigned a) {
    asm volatile("ldmatrix.sync.aligned.m8n8.x4.trans.shared.b16 {%0,%1,%2,%3}, [%4];"
        : "=r"(r0), "=r"(r1), "=r"(r2), "=r"(r3) : "r"(a));
}

#define MMA_BF16(cc, a0,a1,a2,a3, b0,b1) \
    asm volatile("mma.sync.aligned.m16n8k16.row.col.f32.bf16.bf16.f32 " \
        "{%0,%1,%2,%3}, {%4,%5,%6,%7}, {%8,%9}, {%0,%1,%2,%3};" \
        : "+f"(cc[0]), "+f"(cc[1]), "+f"(cc[2]), "+f"(cc[3]) \
        : "r"(a0), "r"(a1), "r"(a2), "r"(a3), "r"(b0), "r"(b1))

// ---------------- K0: zero the stat accumulators ----------------
__global__ void k_zero() {
    int t = threadIdx.x;
    if (t < BATCH) { g_ssum[t]=0.0; g_ssq[t]=0.0; g_csum[t]=0.0; g_csq[t]=0.0; }
}

// ---------------- K2: relative-position bias (6,64,64) ----------------
__global__ void k_bias(const float* __restrict__ m1, const float* __restrict__ b1,
                       const float* __restrict__ m2, const float* __restrict__ b2) {
    int n = blockIdx.x, m = threadIdx.x;            // 64 blocks x 64 threads
    int iyn = n >> 3, ixn = n & 7, iym = m >> 3, ixm = m & 7;
    float d0 = (float)(iyn - iym), d1 = (float)(ixn - ixm);
    float r0 = copysignf(log1pf(fabsf(d0)), d0);
    float r1 = copysignf(log1pf(fabsf(d1)), d1);
    float acc[NHEADS] = {0,0,0,0,0,0};
    for (int j = 0; j < 256; j++) {
        float h = fmaxf(m1[2*j]*r0 + m1[2*j+1]*r1 + b1[j], 0.f);
        #pragma unroll
        for (int hh = 0; hh < NHEADS; hh++) acc[hh] += h * m2[hh*256 + j];
    }
    for (int hh = 0; hh < NHEADS; hh++)
        g_bias[(hh*64 + n)*64 + m] = acc[hh] + b2[hh];
}

// ---------------- convert pe_w1 (256,6144) -> bf16 hi/lo (same layout) ----------------
__global__ void k_cvtw1(const float* __restrict__ w1) {
    size_t o = (size_t)blockIdx.x*256 + threadIdx.x;   // 6144 blocks
    float v = w1[o];
    __nv_bfloat16 h, l; bf_split(v, h, l);
    g_w1h[o] = h; g_w1l[o] = l;
}

// ---------------- K1: QKV 1x1 convs via tensor cores (bf16x3) ----------------
#define SXP 136   // Xs row stride (bf16 elems), padded for conflict-free ldmatrix
#define SWP 104   // Ws row stride
__global__ __launch_bounds__(256) void k_qkvmma(const float* __restrict__ X,
                                                const float* __restrict__ Qw,
                                                const float* __restrict__ Qb,
                                                const float* __restrict__ Vw,
                                                const float* __restrict__ Vb) {
    extern __shared__ __align__(16) __nv_bfloat16 smq[];
    __nv_bfloat16* Xh = smq;                 // 96 x SXP
    __nv_bfloat16* Xl = smq + 96*SXP;
    __nv_bfloat16* Wh = smq + 2*96*SXP;      // 96 x SWP
    __nv_bfloat16* Wl = Wh + 96*SWP;

    int t = threadIdx.x, lane = t & 31, wp = t >> 5;
    int base = blockIdx.x * 128;
    int b = base >> 16, y = (base >> 8) & 255, x0 = base & 255;

    // stage X tile (96 chans x 128 pixels), fp32 -> bf16 hi/lo
    const float* Xg = X + ((size_t)(b*96)*256 + y)*256 + x0;
    #pragma unroll
    for (int r = 0; r < 12; r++) {
        int i = t + 256*r;                  // 0..3071
        int c = i >> 5, p4 = i & 31;
        float4 v = *(const float4*)(Xg + (size_t)c*65536 + p4*4);
        __nv_bfloat16 h0,l0,h1,l1,h2,l2,h3,l3;
        bf_split(v.x,h0,l0); bf_split(v.y,h1,l1); bf_split(v.z,h2,l2); bf_split(v.w,h3,l3);
        *(uint2*)(Xh + c*SXP + p4*4) = make_uint2(pack2(h0,h1), pack2(h2,h3));
        *(uint2*)(Xl + c*SXP + p4*4) = make_uint2(pack2(l0,l1), pack2(l2,l3));
    }

    int wm = (wp >> 1)*32;         // 4 warp-rows of 32 pixels
    int wn = (wp & 1)*48;          // 2 warp-cols of 48 outs
    int wy = y >> 3, iy = y & 7;

    int a_k = (lane & 7) + ((lane >> 4) << 3);
    int a_m = ((lane >> 3) & 1) * 8;
    int b_n = (lane & 7) + ((lane >> 4) << 3);
    int b_k = ((lane >> 3) & 1) * 8;

    for (int ch = 0; ch < 3; ch++) {
        if (ch) __syncthreads();
        const float* Wg = (ch == 2) ? Vw : (Qw + ch*96*96);
        #pragma unroll
        for (int r = 0; r < 9; r++) {
            int i = t + 256*r;              // 0..2303
            int row = i / 24, c4 = i % 24;
            float4 v = *(const float4*)(Wg + row*96 + c4*4);
            __nv_bfloat16 h0,l0,h1,l1,h2,l2,h3,l3;
            bf_split(v.x,h0,l0); bf_split(v.y,h1,l1); bf_split(v.z,h2,l2); bf_split(v.w,h3,l3);
            *(uint2*)(Wh + row*SWP + c4*4) = make_uint2(pack2(h0,h1), pack2(h2,h3));
            *(uint2*)(Wl + row*SWP + c4*4) = make_uint2(pack2(l0,l1), pack2(l2,l3));
        }
        __syncthreads();

        float acc[2][6][4] = {};
        #pragma unroll
        for (int ks = 0; ks < 6; ks++) {
            int k0 = ks*16;
            unsigned ah[2][4], al[2][4];
            #pragma unroll
            for (int mt = 0; mt < 2; mt++) {
                int m0 = wm + mt*16 + a_m;
                ldsm4t(ah[mt][0], ah[mt][1], ah[mt][2], ah[mt][3],
                       s2u(Xh + (k0 + a_k)*SXP + m0));
                ldsm4t(al[mt][0], al[mt][1], al[mt][2], al[mt][3],
                       s2u(Xl + (k0 + a_k)*SXP + m0));
            }
            unsigned bh[6][2], bl[6][2];
            #pragma unroll
            for (int bj = 0; bj < 3; bj++) {
                int nb = wn + bj*16 + b_n;
                unsigned r0,r1,r2,r3;
                ldsm4(r0,r1,r2,r3, s2u(Wh + nb*SWP + k0 + b_k));
                bh[2*bj][0]=r0; bh[2*bj][1]=r1; bh[2*bj+1][0]=r2; bh[2*bj+1][1]=r3;
                ldsm4(r0,r1,r2,r3, s2u(Wl + nb*SWP + k0 + b_k));
                bl[2*bj][0]=r0; bl[2*bj][1]=r1; bl[2*bj+1][0]=r2; bl[2*bj+1][1]=r3;
            }
            #pragma unroll
            for (int mt = 0; mt < 2; mt++)
                #pragma unroll
                for (int nt = 0; nt < 6; nt++) {
                    MMA_BF16(acc[mt][nt], ah[mt][0],ah[mt][1],ah[mt][2],ah[mt][3], bh[nt][0],bh[nt][1]);
                    MMA_BF16(acc[mt][nt], ah[mt][0],ah[mt][1],ah[mt][2],ah[mt][3], bl[nt][0],bl[nt][1]);
                    MMA_BF16(acc[mt][nt], al[mt][0],al[mt][1],al[mt][2],al[mt][3], bh[nt][0],bh[nt][1]);
                }
        }

        const float* bias = (ch == 2) ? Vb : (Qb + ch*96);
        float scl = (ch == 0) ? 0.25f : 1.f;
        float* dst = (ch == 0) ? g_q : (ch == 1) ? g_k : g_v;
        #pragma unroll
        for (int mt = 0; mt < 2; mt++) {
            #pragma unroll
            for (int half = 0; half < 2; half++) {
                int m = wm + mt*16 + (lane >> 2) + half*8;
                int x = x0 + m; int wx = x >> 3, ix = x & 7;
                size_t woff = ((size_t)((b*32 + wy)*32 + wx)*64 + iy*8 + ix)*96;
                #pragma unroll
                for (int nt = 0; nt < 6; nt++) {
                    int d = wn + nt*8 + (lane & 3)*2;
                    float v0 = (acc[mt][nt][half*2 + 0] + bias[d])   * scl;
                    float v1 = (acc[mt][nt][half*2 + 1] + bias[d+1]) * scl;
                    *(float2*)(dst + woff + d) = make_float2(v0, v1);
                }
            }
        }
    }
}

// ---------------- K3: window attention (online softmax, 4 keys/step, 2 queries/thread) ----------------
// 192 threads = 6 heads x 32 lanes; lane handles queries n and n+32 -> halves smem traffic.
__global__ __launch_bounds__(192) void k_attn() {
    __shared__ __align__(16) float sm[2*FEAT];      // 48KB: K tile, V tile
    float* Ks = sm; float* Vs = sm + FEAT;
    int w = blockIdx.x; int tid = threadIdx.x;      // 192 threads
    int b = w >> 10;
    const float4* kg = (const float4*)(g_k + (size_t)w*FEAT);
    const float4* vg = (const float4*)(g_v + (size_t)w*FEAT);
    for (int i = tid; i < FEAT/4; i += 192) { ((float4*)Ks)[i] = kg[i]; ((float4*)Vs)[i] = vg[i]; }
    int h = tid >> 5, n0 = tid & 31, n1 = n0 + 32;
    float q0[HD], q1[HD];
    const float* qg0 = g_q + ((size_t)w*NTOK + n0)*CH + h*HD;
    const float* qg1 = g_q + ((size_t)w*NTOK + n1)*CH + h*HD;
    #pragma unroll
    for (int d4 = 0; d4 < 4; d4++) {
        *(float4*)(q0 + d4*4) = *(const float4*)(qg0 + d4*4);
        *(float4*)(q1 + d4*4) = *(const float4*)(qg1 + d4*4);
    }
    __syncthreads();
    const float* bs0 = g_bias + (h*64 + n0)*64;
    const float* bs1 = g_bias + (h*64 + n1)*64;
    float mx0 = -1e30f, l0 = 0.f, mx1 = -1e30f, l1 = 0.f;
    float o0[HD], o1[HD];
    #pragma unroll
    for (int d = 0; d < HD; d++) { o0[d] = 0.f; o1[d] = 0.f; }
    for (int m = 0; m < 64; m += 4) {
        float s0[4], s1[4];
        #pragma unroll
        for (int j = 0; j < 4; j++) {
            const float4* kr = (const float4*)(Ks + (m + j)*CH + h*HD);
            float a0 = bs0[m + j], a1 = bs1[m + j];
            #pragma unroll
            for (int d4 = 0; d4 < 4; d4++) {
                float4 kv = kr[d4];
                a0 += q0[d4*4]*kv.x + q0[d4*4+1]*kv.y + q0[d4*4+2]*kv.z + q0[d4*4+3]*kv.w;
                a1 += q1[d4*4]*kv.x + q1[d4*4+1]*kv.y + q1[d4*4+2]*kv.z + q1[d4*4+3]*kv.w;
            }
            s0[j] = a0; s1[j] = a1;
        }
        float nm0 = fmaxf(mx0, fmaxf(fmaxf(s0[0], s0[1]), fmaxf(s0[2], s0[3])));
        float nm1 = fmaxf(mx1, fmaxf(fmaxf(s1[0], s1[1]), fmaxf(s1[2], s1[3])));
        float c0 = __expf(mx0 - nm0);
        float c1 = __expf(mx1 - nm1);
        float p00 = __expf(s0[0] - nm0), p01 = __expf(s0[1] - nm0);
        float p02 = __expf(s0[2] - nm0), p03 = __expf(s0[3] - nm0);
        float p10 = __expf(s1[0] - nm1), p11 = __expf(s1[1] - nm1);
        float p12 = __expf(s1[2] - nm1), p13 = __expf(s1[3] - nm1);
        l0 = l0*c0 + p00 + p01 + p02 + p03;
        l1 = l1*c1 + p10 + p11 + p12 + p13;
        const float4* vr0 = (const float4*)(Vs + m*CH + h*HD);
        const float4* vr1 = (const float4*)(Vs + (m+1)*CH + h*HD);
        const float4* vr2 = (const float4*)(Vs + (m+2)*CH + h*HD);
        const float4* vr3 = (const float4*)(Vs + (m+3)*CH + h*HD);
        #pragma unroll
        for (int d4 = 0; d4 < 4; d4++) {
            float4 v0 = vr0[d4], v1 = vr1[d4], v2 = vr2[d4], v3 = vr3[d4];
            o0[d4*4]   = o0[d4*4]*c0   + p00*v0.x + p01*v1.x + p02*v2.x + p03*v3.x;
            o0[d4*4+1] = o0[d4*4+1]*c0 + p00*v0.y + p01*v1.y + p02*v2.y + p03*v3.y;
            o0[d4*4+2] = o0[d4*4+2]*c0 + p00*v0.z + p01*v1.z + p02*v2.z + p03*v3.z;
            o0[d4*4+3] = o0[d4*4+3]*c0 + p00*v0.w + p01*v1.w + p02*v2.w + p03*v3.w;
            o1[d4*4]   = o1[d4*4]*c1   + p10*v0.x + p11*v1.x + p12*v2.x + p13*v3.x;
            o1[d4*4+1] = o1[d4*4+1]*c1 + p10*v0.y + p11*v1.y + p12*v2.y + p13*v3.y;
            o1[d4*4+2] = o1[d4*4+2]*c1 + p10*v0.z + p11*v1.z + p12*v2.z + p13*v3.z;
            o1[d4*4+3] = o1[d4*4+3]*c1 + p10*v0.w + p11*v1.w + p12*v2.w + p13*v3.w;
        }
        mx0 = nm0; mx1 = nm1;
    }
    float inv0 = 1.f / l0, inv1 = 1.f / l1;
    size_t i0 = ((size_t)w*NTOK + n0)*CH + h*HD;
    size_t i1 = ((size_t)w*NTOK + n1)*CH + h*HD;
    float ls = 0.f, lq = 0.f;
    #pragma unroll
    for (int d = 0; d < HD; d++) {
        float v0 = o0[d]*inv0, v1 = o1[d]*inv1;
        ls += v0 + v1; lq += v0*v0 + v1*v1;
        __nv_bfloat16 bh, bl;
        bf_split(v0, bh, bl); g_aw_h[i0 + d] = bh; g_aw_l[i0 + d] = bl;
        bf_split(v1, bh, bl); g_aw_h[i1 + d] = bh; g_aw_l[i1 + d] = bl;
    }
    double ds = ls, dq = lq;
    for (int off = 16; off; off >>= 1) {
        ds += __shfl_down_sync(0xffffffffu, ds, off);
        dq += __shfl_down_sync(0xffffffffu, dq, off);
    }
    __syncthreads();                                 // all Ks/Vs reads done
    double* red = (double*)sm;
    int wid = tid >> 5, lane = tid & 31;
    if (lane == 0) { red[wid] = ds; red[6 + wid] = dq; }
    __syncthreads();
    if (tid == 0) {
        double a = 0, c = 0;
        for (int i = 0; i < 6; i++) { a += red[i]; c += red[6 + i]; }
        atomicAdd(&g_ssum[b], a); atomicAdd(&g_ssq[b], c);
    }
}

// ---------------- tensor-core GEMM (bf16x3) with ldmatrix fragments ----------------
// MODE 0: split-K partials of (aw @ w1^T) -> g_Hp[z]   (B [n][k], non-trans ldsm)
// MODE 1: rw = (attg @ aw)*scale + shift               (B [k][n], trans ldsm)
template<int MODE>
__global__ __launch_bounds__(256, 2) void k_tcgemm(const float* __restrict__ bias) {
    constexpr int K    = (MODE == 0) ? FEAT : NWIN;
    constexpr int Ndim = (MODE == 0) ? 256  : FEAT;
    constexpr int ASZ  = 128*40;
    constexpr int BSZ  = (MODE == 0) ? 128*40 : 32*136;
    extern __shared__ __align__(16) __nv_bfloat16 smbuf[];
    __nv_bfloat16* Ab = smbuf;            // [stage*2+hl][ASZ]
    __nv_bfloat16* Bb = smbuf + 4*ASZ;    // [stage*2+hl][BSZ]

    const __nv_bfloat16 *Ah, *Al, *Bh, *Bl;
    float* C;
    if (MODE == 0) {
        Ah = g_aw_h; Al = g_aw_l; Bh = g_w1h; Bl = g_w1l;
        C = g_Hp + (size_t)blockIdx.z*NWTOT*256;
    } else {
        size_t z = blockIdx.z;
        Ah = g_attg_h + z*NWIN*NWIN; Al = g_attg_l + z*NWIN*NWIN;
        Bh = g_aw_h + z*NWIN*FEAT;  Bl = g_aw_l + z*NWIN*FEAT;
        C  = g_rw   + z*NWIN*FEAT;
    }
    int m0 = blockIdx.y*128, n0 = blockIdx.x*128;
    int t = threadIdx.x;

#define LOAD_STAGE(st, kb) { \
    int arr = t >> 6, tt = t & 63; \
    if (arr < 2) { \
        const __nv_bfloat16* g = arr ? Al : Ah; \
        _Pragma("unroll") \
        for (int rr = 0; rr < 2; rr++) { \
            int r = tt*2 + rr; \
            const __nv_bfloat16* src = g + (size_t)(m0 + r)*K + (kb); \
            unsigned dstb = s2u(Ab + ((st)*2+arr)*ASZ + r*40); \
            _Pragma("unroll") \
            for (int seg = 0; seg < 4; seg++) \
                asm volatile("cp.async.cg.shared.global [%0], [%1], 16;" \
                    :: "r"(dstb + seg*16), "l"(src + seg*8)); \
        } \
    } else { \
        int hl = arr - 2; \
        const __nv_bfloat16* g = hl ? Bl : Bh; \
        if (MODE == 0) { \
            _Pragma("unroll") \
            for (int rr = 0; rr < 2; rr++) { \
                int r = tt*2 + rr; \
                const __nv_bfloat16* src = g + (size_t)(n0 + r)*K + (kb); \
                unsigned dstb = s2u(Bb + ((st)*2+hl)*BSZ + r*40); \
                _Pragma("unroll") \
                for (int seg = 0; seg < 4; seg++) \
                    asm volatile("cp.async.cg.shared.global [%0], [%1], 16;" \
                        :: "r"(dstb + seg*16), "l"(src + seg*8)); \
            } \
        } else { \
            _Pragma("unroll") \
            for (int j = 0; j < 8; j++) { \
                int idx = tt*8 + j; \
                int row = idx >> 4, col = idx & 15; \
                const __nv_bfloat16* src = g + (size_t)((kb) + row)*FEAT + n0 + col*8; \
                unsigned dstb = s2u(Bb + ((st)*2+hl)*BSZ + row*136 + col*8); \
                asm volatile("cp.async.cg.shared.global [%0], [%1], 16;" \
                    :: "r"(dstb), "l"(src)); \
            } \
        } \
    } \
    asm volatile("cp.async.commit_group;"); }

    float acc[4][4][4];
    #pragma unroll
    for (int i = 0; i < 4; i++)
        #pragma unroll
        for (int j = 0; j < 4; j++)
            #pragma unroll
            for (int q = 0; q < 4; q++) acc[i][j][q] = 0.f;

    int lane = t & 31, wp = t >> 5;
    int wm = (wp >> 2)*64, wn = (wp & 3)*32;

    // fragment lane addressing (verified mappings)
    int a_m = lane & 15, a_k = (lane >> 4)*8;                       // A non-trans
    int b_n = (lane & 7) + ((lane >> 4) << 3), b_k = ((lane >> 3) & 1)*8;   // B non-trans [n][k]
    int tb_k = (lane & 7) + ((lane >> 3) & 1)*8, tb_n = (lane >> 4)*8;      // B trans [k][n]

    constexpr int NK = (MODE == 0) ? (FEAT/4)/32 : K/32;
    int koff = (MODE == 0) ? blockIdx.z*(FEAT/4) : 0;
    LOAD_STAGE(0, koff);
    for (int c = 0; c < NK; c++) {
        if (c + 1 < NK) {
            LOAD_STAGE((c+1)&1, koff + (c+1)*32);
            asm volatile("cp.async.wait_group 1;");
        } else {
            asm volatile("cp.async.wait_group 0;");
        }
        __syncthreads();
        int st = c & 1;
        const __nv_bfloat16* sah = Ab + (st*2+0)*ASZ;
        const __nv_bfloat16* sal = Ab + (st*2+1)*ASZ;
        const __nv_bfloat16* sbh = Bb + (st*2+0)*BSZ;
        const __nv_bfloat16* sbl = Bb + (st*2+1)*BSZ;
        #pragma unroll
        for (int ks = 0; ks < 2; ks++) {
            unsigned ah[4][4], bh[4][2], bl[4][2];
            #pragma unroll
            for (int i = 0; i < 4; i++)
                ldsm4(ah[i][0], ah[i][1], ah[i][2], ah[i][3],
                      s2u(sah + (wm + i*16 + a_m)*40 + ks*16 + a_k));
            if (MODE == 0) {
                #pragma unroll
                for (int bj = 0; bj < 2; bj++) {
                    unsigned r0,r1,r2,r3;
                    ldsm4(r0,r1,r2,r3, s2u(sbh + (wn + bj*16 + b_n)*40 + ks*16 + b_k));
                    bh[2*bj][0]=r0; bh[2*bj][1]=r1; bh[2*bj+1][0]=r2; bh[2*bj+1][1]=r3;
                    ldsm4(r0,r1,r2,r3, s2u(sbl + (wn + bj*16 + b_n)*40 + ks*16 + b_k));
                    bl[2*bj][0]=r0; bl[2*bj][1]=r1; bl[2*bj+1][0]=r2; bl[2*bj+1][1]=r3;
                }
            } else {
                #pragma unroll
                for (int bj = 0; bj < 2; bj++) {
                    unsigned r0,r1,r2,r3;
                    ldsm4t(r0,r1,r2,r3, s2u(sbh + (ks*16 + tb_k)*136 + wn + bj*16 + tb_n));
                    bh[2*bj][0]=r0; bh[2*bj][1]=r1; bh[2*bj+1][0]=r2; bh[2*bj+1][1]=r3;
                    ldsm4t(r0,r1,r2,r3, s2u(sbl + (ks*16 + tb_k)*136 + wn + bj*16 + tb_n));
                    bl[2*bj][0]=r0; bl[2*bj][1]=r1; bl[2*bj+1][0]=r2; bl[2*bj+1][1]=r3;
                }
            }
            // pass 1+2: hi*hi, hi*lo
            #pragma unroll
            for (int j = 0; j < 4; j++)
                #pragma unroll
                for (int i = 0; i < 4; i++) {
                    MMA_BF16(acc[i][j], ah[i][0], ah[i][1], ah[i][2], ah[i][3], bh[j][0], bh[j][1]);
                    MMA_BF16(acc[i][j], ah[i][0], ah[i][1], ah[i][2], ah[i][3], bl[j][0], bl[j][1]);
                }
            // pass 3: lo*hi (load al after ah is dead)
            unsigned al[4][4];
            #pragma unroll
            for (int i = 0; i < 4; i++)
                ldsm4(al[i][0], al[i][1], al[i][2], al[i][3],
                      s2u(sal + (wm + i*16 + a_m)*40 + ks*16 + a_k));
            #pragma unroll
            for (int j = 0; j < 4; j++)
                #pragma unroll
                for (int i = 0; i < 4; i++)
                    MMA_BF16(acc[i][j], al[i][0], al[i][1], al[i][2], al[i][3], bh[j][0], bh[j][1]);
        }
        __syncthreads();
    }

    float gsc = 1.f, gof = 0.f;
    if (MODE == 1) { gsc = g_scale[blockIdx.z]; gof = g_shift[blockIdx.z]; }
    #pragma unroll
    for (int i = 0; i < 4; i++) {
        int row = m0 + wm + i*16 + (lane >> 2);
        #pragma unroll
        for (int j = 0; j < 4; j++) {
            int col = n0 + wn + j*8 + (lane & 3)*2;
            float* cc = acc[i][j];
            if (MODE == 0) {
                // raw split-K partials (bias+relu applied in k_redH)
                *(float2*)(C + (size_t)row*Ndim + col)     = make_float2(cc[0], cc[1]);
                *(float2*)(C + (size_t)(row+8)*Ndim + col) = make_float2(cc[2], cc[3]);
            } else {
                float2 v0 = make_float2(cc[0]*gsc+gof, cc[1]*gsc+gof);
                float2 v1 = make_float2(cc[2]*gsc+gof, cc[3]*gsc+gof);
                *(float2*)(C + (size_t)row*Ndim + col)     = v0;
                *(float2*)(C + (size_t)(row+8)*Ndim + col) = v1;
            }
        }
    }
#undef LOAD_STAGE
}

// ---------------- reduce split-K partials: H = relu(sum_z Hp[z] + b1) ----------------
__global__ void k_redH(const float* __restrict__ b1v) {
    size_t o = (size_t)blockIdx.x*256 + threadIdx.x;    // 4096 blocks x 256 thr
    const size_t STRIDE = (size_t)NWTOT*256;
    float s = g_Hp[o] + g_Hp[o + STRIDE] + g_Hp[o + 2*STRIDE] + g_Hp[o + 3*STRIDE];
    g_H[o] = fmaxf(s + b1v[threadIdx.x], 0.f);
}

// ---------------- K4b: emb = l2norm(H @ pe_w2^T + b2) -> embT + cur stats ----------------
__global__ void k_emb(const float* __restrict__ w2, const float* __restrict__ b2) {
    __shared__ float hs[256];
    int w = blockIdx.x; int t = threadIdx.x;        // 32 threads
    const float* hr = g_H + (size_t)w*256;
    for (int i = t; i < 256; i += 32) hs[i] = hr[i];
    __syncwarp();
    float e = 0.f;
    if (t < PDIM) {
        e = b2[t];
        const float* wr = w2 + t*256;
        for (int j = 0; j < 256; j++) e += hs[j]*wr[j];
    }
    float sq = e*e;
    for (int off = 16; off; off >>= 1) sq += __shfl_down_sync(0xffffffffu, sq, off);
    sq = __shfl_sync(0xffffffffu, sq, 0);
    float inv = 1.f / (sqrtf(sq) + EPSV);
    e *= inv;
    if (t < PDIM) g_embT[(size_t)t*NWTOT + w] = e;
    double d1 = (t < PDIM) ? (double)e : 0.0;
    double d2 = (t < PDIM) ? (double)(e*e) : 0.0;
    for (int off = 16; off; off >>= 1) {
        d1 += __shfl_down_sync(0xffffffffu, d1, off);
        d2 += __shfl_down_sync(0xffffffffu, d2, off);
    }
    if (t == 0) { int b = w >> 10; atomicAdd(&g_csum[b], d1); atomicAdd(&g_csq[b], d2); }
}

// ---------------- finalize per-batch affine (scale/shift) ----------------
__global__ void k_fin() {
    int b = threadIdx.x; if (b >= BATCH) return;
    double ns = (double)NWIN * FEAT;
    double sm = g_ssum[b]/ns, sv = g_ssq[b]/ns - sm*sm;
    float sstd = sqrtf((float)sv + EPSV);
    double nc = (double)NWIN * PDIM;
    double cm = g_csum[b]/nc, cv = g_csq[b]/nc - cm*cm;
    float cstd = sqrtf((float)cv + EPSV);
    float g = sstd / cstd;
    g_scale[b] = g;
    g_shift[b] = (float)sm - (float)cm * g;
}

// ---------------- K5: att_g = l1norm(exp(a*emb@emb^T + c)) -> bf16 hi/lo ----------------
__global__ void k_attg(const float* __restrict__ alpha, const float* __restrict__ beta) {
    __shared__ float en[PDIM];
    __shared__ float red[256];
    int b = blockIdx.y, n = blockIdx.x, t = threadIdx.x;  // 256 threads
    if (t < PDIM) en[t] = g_embT[(size_t)t*NWTOT + b*NWIN + n];
    __syncthreads();
    float a = 30.f * alpha[0], c = 20.f * beta[0];
    float v[4]; float s = 0.f;
    #pragma unroll
    for (int r = 0; r < 4; r++) {
        int m = t + r*256;
        float d = 0.f;
        #pragma unroll
        for (int j = 0; j < PDIM; j++)
            d += en[j] * g_embT[(size_t)j*NWTOT + b*NWIN + m];
        float ev = __expf(a*d + c);
        v[r] = ev; s += ev;
    }
    red[t] = s; __syncthreads();
    for (int off = 128; off; off >>= 1) { if (t < off) red[t] += red[t + off]; __syncthreads(); }
    float inv = 1.f / (red[0] + EPSV);
    size_t rbase = ((size_t)(b*NWIN + n))*NWIN;
    #pragma unroll
    for (int r = 0; r < 4; r++) {
        float vv = v[r]*inv;
        __nv_bfloat16 bh, bl; bf_split(vv, bh, bl);
        g_attg_h[rbase + t + r*256] = bh;
        g_attg_l[rbase + t + r*256] = bl;
    }
}

// ---------------- K7: depthwise 5x5 (reflect) + window-reverse gather -> S ----------------
#define CVP 145
__global__ __launch_bounds__(384) void k_conv(const float* __restrict__ dww,
                                              const float* __restrict__ dwb) {
    __shared__ float sv[48*CVP];                     // 48 channels x 12x12 halo (padded)
    __shared__ float sw[48*25];
    int blk = blockIdx.x; int w = blk >> 1, half = blk & 1;
    int b = w >> 10, wy = (w >> 5) & 31, wx = w & 31;
    int y0 = wy*8, x0 = wx*8;
    int t = threadIdx.x;                             // 384 threads
    for (int i = t; i < 48*25; i += 384) sw[i] = dww[half*48*25 + i];
    for (int i = t; i < 48*144; i += 384) {
        int cl = i % 48, pidx = i / 48;
        int gy = y0 - 2 + pidx/12, gx = x0 - 2 + pidx%12;
        gy = gy < 0 ? -gy : (gy > 255 ? 510 - gy : gy);
        gx = gx < 0 ? -gx : (gx > 255 ? 510 - gx : gx);
        int wyp = gy >> 3, wxp = gx >> 3, widx = (gy & 7)*8 + (gx & 7);
        sv[cl*CVP + pidx] =
            g_v[(((size_t)((b*32 + wyp)*32 + wxp))*64 + widx)*96 + half*48 + cl];
    }
    __syncthreads();
    int c = t % 48, g = t / 48;                      // channel, window row
    int cg = half*48 + c;
    float wreg[25];
    #pragma unroll
    for (int k2 = 0; k2 < 25; k2++) wreg[k2] = sw[c*25 + k2];
    float acc[8];
    float bb = dwb[cg];
    #pragma unroll
    for (int ix = 0; ix < 8; ix++) acc[ix] = bb;
    const float* svc = sv + c*CVP;
    #pragma unroll
    for (int ky = 0; ky < 5; ky++) {
        float row[12];
        #pragma unroll
        for (int xx = 0; xx < 12; xx++) row[xx] = svc[(g + ky)*12 + xx];
        #pragma unroll
        for (int kx = 0; kx < 5; kx++) {
            float wv = wreg[ky*5 + kx];
            #pragma unroll
            for (int ix = 0; ix < 8; ix++) acc[ix] += wv*row[ix + kx];
        }
    }
    const float* rwb = g_rw + (size_t)w*FEAT;
    #pragma unroll
    for (int ix = 0; ix < 8; ix++) {
        int pix = g*8 + ix;
        g_S[((size_t)(b*IMG + y0 + g)*IMG + x0 + ix)*CH + cg] = acc[ix] + rwb[pix*CH + cg];
    }
}

// ---------------- K8: out = proj(S) + proj_b via tensor cores (bf16x3) ----------------
#define SSP 104   // Ss row stride
#define OSP 136   // Os row stride (fp32)
__global__ __launch_bounds__(256) void k_projmma(const float* __restrict__ pw,
                                                 const float* __restrict__ pb,
                                                 float* __restrict__ out) {
    extern __shared__ __align__(16) __nv_bfloat16 smp[];
    __nv_bfloat16* Sh = smp;                 // 128 x SSP
    __nv_bfloat16* Sl = smp + 128*SSP;
    __nv_bfloat16* Wh = smp + 2*128*SSP;     // 96 x SSP
    __nv_bfloat16* Wl = Wh + 96*SSP;
    float* Os = (float*)smp;                 // aliased after compute: 96 x OSP

    int t = threadIdx.x, lane = t & 31, wp = t >> 5;
    int base = blockIdx.x * 128;
    int b = base >> 16, y = (base >> 8) & 255, x0 = base & 255;

    const float* Sg = g_S + (size_t)base*96;
    #pragma unroll
    for (int r = 0; r < 12; r++) {
        int i = t + 256*r;
        int row = i / 24, c4 = i % 24;
        float4 v = *(const float4*)(Sg + (size_t)row*96 + c4*4);
        __nv_bfloat16 h0,l0,h1,l1,h2,l2,h3,l3;
        bf_split(v.x,h0,l0); bf_split(v.y,h1,l1); bf_split(v.z,h2,l2); bf_split(v.w,h3,l3);
        *(uint2*)(Sh + row*SSP + c4*4) = make_uint2(pack2(h0,h1), pack2(h2,h3));
        *(uint2*)(Sl + row*SSP + c4*4) = make_uint2(pack2(l0,l1), pack2(l2,l3));
    }
    #pragma unroll
    for (int r = 0; r < 9; r++) {
        int i = t + 256*r;
        int row = i / 24, c4 = i % 24;
        float4 v = *(const float4*)(pw + row*96 + c4*4);
        __nv_bfloat16 h0,l0,h1,l1,h2,l2,h3,l3;
        bf_split(v.x,h0,l0); bf_split(v.y,h1,l1); bf_split(v.z,h2,l2); bf_split(v.w,h3,l3);
        *(uint2*)(Wh + row*SSP + c4*4) = make_uint2(pack2(h0,h1), pack2(h2,h3));
        *(uint2*)(Wl + row*SSP + c4*4) = make_uint2(pack2(l0,l1), pack2(l2,l3));
    }
    __syncthreads();

    int wm = (wp >> 1)*32, wn = (wp & 1)*48;
    int a_m = (lane & 7) + ((lane >> 3) & 1)*8;
    int a_k = (lane >> 4)*8;
    int b_n = (lane & 7) + ((lane >> 4) << 3);
    int b_k = ((lane >> 3) & 1)*8;

    float acc[2][6][4] = {};
    #pragma unroll
    for (int ks = 0; ks < 6; ks++) {
        int k0 = ks*16;
        unsigned ah[2][4], al[2][4];
        #pragma unroll
        for (int mt = 0; mt < 2; mt++) {
            int m0 = wm + mt*16 + a_m;
            ldsm4(ah[mt][0], ah[mt][1], ah[mt][2], ah[mt][3], s2u(Sh + m0*SSP + k0 + a_k));
            ldsm4(al[mt][0], al[mt][1], al[mt][2], al[mt][3], s2u(Sl + m0*SSP + k0 + a_k));
        }
        unsigned bh[6][2], bl[6][2];
        #pragma unroll
        for (int bj = 0; bj < 3; bj++) {
            int nb = wn + bj*16 + b_n;
            unsigned r0,r1,r2,r3;
            ldsm4(r0,r1,r2,r3, s2u(Wh + nb*SSP + k0 + b_k));
            bh[2*bj][0]=r0; bh[2*bj][1]=r1; bh[2*bj+1][0]=r2; bh[2*bj+1][1]=r3;
            ldsm4(r0,r1,r2,r3, s2u(Wl + nb*SSP + k0 + b_k));
            bl[2*bj][0]=r0; bl[2*bj][1]=r1; bl[2*bj+1][0]=r2; bl[2*bj+1][1]=r3;
        }
        #pragma unroll
        for (int mt = 0; mt < 2; mt++)
            #pragma unroll
            for (int nt = 0; nt < 6; nt++) {
                MMA_BF16(acc[mt][nt], ah[mt][0],ah[mt][1],ah[mt][2],ah[mt][3], bh[nt][0],bh[nt][1]);
                MMA_BF16(acc[mt][nt], ah[mt][0],ah[mt][1],ah[mt][2],ah[mt][3], bl[nt][0],bl[nt][1]);
                MMA_BF16(acc[mt][nt], al[mt][0],al[mt][1],al[mt][2],al[mt][3], bh[nt][0],bh[nt][1]);
            }
    }
    __syncthreads();
    #pragma unroll
    for (int mt = 0; mt < 2; mt++)
        #pragma unroll
        for (int half = 0; half < 2; half++) {
            int m = wm + mt*16 + (lane >> 2) + half*8;
            #pragma unroll
            for (int nt = 0; nt < 6; nt++) {
                int d = wn + nt*8 + (lane & 3)*2;
                Os[d*OSP + m]     = acc[mt][nt][half*2 + 0];
                Os[(d+1)*OSP + m] = acc[mt][nt][half*2 + 1];
            }
        }
    __syncthreads();
    #pragma unroll
    for (int r = 0; r < 12; r++) {
        int i = t + 256*r;
        int d = i >> 5, p4 = i & 31;
        float4 v = *(const float4*)(Os + d*OSP + p4*4);
        float bb = pb[d];
        v.x += bb; v.y += bb; v.z += bb; v.w += bb;
        *(float4*)(out + ((size_t)(b*96 + d))*65536 + y*256 + x0 + p4*4) = v;
    }
}

// ---------------- host ----------------
extern "C" void kernel_launch(void* const* d_in, const int* in_sizes, int n_in,
                              void* d_out, int out_size) {
    const float* X     = (const float*)d_in[0];
    const float* V_w   = (const float*)d_in[1];
    const float* V_b   = (const float*)d_in[2];
    const float* QK_w  = (const float*)d_in[3];
    const float* QK_b  = (const float*)d_in[4];
    const float* proj_w= (const float*)d_in[5];
    const float* proj_b= (const float*)d_in[6];
    const float* dw_w  = (const float*)d_in[7];
    const float* dw_b  = (const float*)d_in[8];
    const float* m_w1  = (const float*)d_in[9];
    const float* m_b1  = (const float*)d_in[10];
    const float* m_w2  = (const float*)d_in[11];
    const float* m_b2  = (const float*)d_in[12];
    const float* pe_w1 = (const float*)d_in[13];
    const float* pe_b1 = (const float*)d_in[14];
    const float* pe_w2 = (const float*)d_in[15];
    const float* pe_b2 = (const float*)d_in[16];
    const float* a_al  = (const float*)d_in[17];
    const float* a_be  = (const float*)d_in[18];
    float* out = (float*)d_out;

    const int TCSMEM0  = (4*128*40 + 4*128*40)*2;         // 81920 bytes
    const int TCSMEM1  = (4*128*40 + 4*32*136)*2;         // 75776 bytes
    const int QKVSMEM  = (2*96*SXP + 2*96*SWP)*2;         // 92160 bytes
    const int PROJSMEM = (2*128*SSP + 2*96*SSP)*2;        // 93184 bytes
    cudaFuncSetAttribute(k_tcgemm<0>, cudaFuncAttributeMaxDynamicSharedMemorySize, TCSMEM0);
    cudaFuncSetAttribute(k_tcgemm<1>, cudaFuncAttributeMaxDynamicSharedMemorySize, TCSMEM1);
    cudaFuncSetAttribute(k_qkvmma,    cudaFuncAttributeMaxDynamicSharedMemorySize, QKVSMEM);
    cudaFuncSetAttribute(k_projmma,   cudaFuncAttributeMaxDynamicSharedMemorySize, PROJSMEM);

    // launch order: k_attn at slot 4 (= the ncu capture slot) to verify the fix
    k_qkvmma<<<NPIX/128, 256, QKVSMEM>>>(X, QK_w, QK_b, V_w, V_b);   // 1
    k_bias<<<64, 64>>>(m_w1, m_b1, m_w2, m_b2);                      // 2
    k_zero<<<1, 32>>>();                                             // 3
    k_attn<<<NWTOT, 192>>>();                                        // 4 <- profiled
    k_cvtw1<<<6144, 256>>>(pe_w1);                                   // 5
    k_tcgemm<0><<<dim3(2, 32, 4), 256, TCSMEM0>>>(nullptr);          // split-K partials
    k_redH<<<NWTOT, 256>>>(pe_b1);                                   // H = relu(sum + b1)
    k_emb<<<NWTOT, 32>>>(pe_w2, pe_b2);
    k_fin<<<1, 32>>>();
    k_attg<<<dim3(NWIN, BATCH), 256>>>(a_al, a_be);
    k_tcgemm<1><<<dim3(FEAT/128, NWIN/128, BATCH), 256, TCSMEM1>>>(nullptr); // rw
    k_conv<<<NWTOT*2, 384>>>(dw_w, dw_b);
    k_projmma<<<NPIX/128, 256, PROJSMEM>>>(proj_w, proj_b, out);
}